// round 7
// baseline (speedup 1.0000x reference)
#include <cuda_runtime.h>
#include <cstdint>

#define CRF_B 1024
#define CRF_S 512
#define CRF_T 64

__device__ float g_partial[CRF_B];
__device__ unsigned int g_count = 0;

__device__ __forceinline__ float ex2f(float x) {
    float y; asm("ex2.approx.ftz.f32 %0, %1;" : "=f"(y) : "f"(x)); return y;
}
__device__ __forceinline__ float lg2f(float x) {
    float y; asm("lg2.approx.f32 %0, %1;" : "=f"(y) : "f"(x)); return y;
}
__device__ __forceinline__ unsigned long long fma2(unsigned long long a,
                                                   unsigned long long b,
                                                   unsigned long long c) {
    unsigned long long d;
    asm("fma.rn.f32x2 %0, %1, %2, %3;" : "=l"(d) : "l"(a), "l"(b), "l"(c));
    return d;
}
__device__ __forceinline__ unsigned long long add2(unsigned long long a,
                                                   unsigned long long b) {
    unsigned long long d;
    asm("add.rn.f32x2 %0, %1, %2;" : "=l"(d) : "l"(a), "l"(b));
    return d;
}
__device__ __forceinline__ unsigned long long pack2(float lo, float hi) {
    unsigned long long d;
    asm("mov.b64 %0, {%1, %2};" : "=l"(d) : "f"(lo), "f"(hi));
    return d;
}
__device__ __forceinline__ void unpack2(float& lo, float& hi, unsigned long long v) {
    asm("mov.b64 {%0, %1}, %2;" : "=f"(lo), "=f"(hi) : "l"(v));
}

// One CTA (64 threads) per batch element; thread j owns state j.
// Scaled linear-domain forward algorithm. Renormalization uses integer
// exponent extraction (exact 2^-K), computed OFF the serial chain.
// Per-step chain: bar -> LDS p -> FMA2 tree -> 1 FMUL -> STS -> bar.
__global__ void __launch_bounds__(CRF_T) crf_scan_kernel(
    const float* __restrict__ inputs,        // [B, S, T]
    const float* __restrict__ trans,         // [T, T]
    const unsigned char* __restrict__ masks, // [B, S]
    const int* __restrict__ tags,            // [B, S]
    float* __restrict__ out, int out_size)
{
    const int b = blockIdx.x;
    const int j = threadIdx.x;
    const float L = 1.4426950408889634f;  // log2(e)

    __shared__ __align__(16) float p_sh[2][CRF_T];
    __shared__ float red[CRF_T];
    __shared__ int tag_sh[CRF_S];
    __shared__ unsigned char mask_sh[CRF_S];
    __shared__ bool is_last;

    const float* xb = inputs + (size_t)b * CRF_S * CRF_T;
    const int* tg = tags + (size_t)b * CRF_S;
    const unsigned char* mk = masks + (size_t)b * CRF_S;

    for (int s = j; s < CRF_S; s += CRF_T) {
        tag_sh[s] = tg[s];
        mask_sh[s] = mk[s];
    }
    __syncthreads();

    // unary + binary partial sums (strided over s)
    float ub = 0.f;
    for (int s = j; s < CRF_S; s += CRF_T) {
        if (!mask_sh[s]) {
            ub += xb[s * CRF_T + tag_sh[s]];
            if (s >= 1) ub += trans[tag_sh[s - 1] * CRF_T + tag_sh[s]];
        }
    }

    // E2[k] = packed { e^trans[2k][j], e^trans[2k+1][j] }
    unsigned long long E2[CRF_T / 2];
#pragma unroll
    for (int k = 0; k < CRF_T / 2; k++) {
        float e0 = ex2f(L * trans[(2 * k) * CRF_T + j]);
        float e1 = ex2f(L * trans[(2 * k + 1) * CRF_T + j]);
        E2[k] = pack2(e0, e1);
    }

    // Init: stored p = 2^(L*x0_j - A), running scale Kacc = A (base-2).
    float A = L * xb[0];
    float pj = ex2f(fmaf(L, xb[j], -A));
    float Kacc = A;
    p_sh[0][j] = pj;

    // x pipeline: xf_cur = 2^(L*x_t) ready at step t; 2-deep raw prefetch.
    float xf_cur  = ex2f(L * xb[1 * CRF_T + j]);
    float xraw_n  = xb[2 * CRF_T + j];
    __syncthreads();

#pragma unroll 1
    for (int t = 1; t < CRF_S; t++) {
        const int pb = (t - 1) & 1;

        // ---- off-chain work first (deferred barrier lets these issue) ----
        int idx2 = (t + 2 < CRF_S) ? (t + 2) : (CRF_S - 1);
        float xraw_2 = xb[idx2 * CRF_T + j];      // prefetch t+2
        float xf_nx = ex2f(L * xraw_n);           // MUFU for step t+1
        unsigned char m = mask_sh[t];

        // scalar broadcast read of p0 -> exact power-of-2 renorm factor
        float p0 = p_sh[pb][0];
        int K = ((__float_as_int(p0) >> 23) & 0xFF) - 127;
        float scale = __int_as_float((127 - K) << 23);  // 2^-K
        float comb = xf_cur * scale;

        // ---- dot product: 8 chains x 4 FMA2 ----
        const ulonglong2* pq = reinterpret_cast<const ulonglong2*>(p_sh[pb]);
        unsigned long long acc[8];
#pragma unroll
        for (int c = 0; c < 8; c++) acc[c] = 0ull;
#pragma unroll
        for (int i = 0; i < 16; i++) {
            ulonglong2 q = pq[i];   // packed pairs 2i, 2i+1
            acc[i >> 1] = fma2(q.x, E2[2 * i], acc[i >> 1]);
            acc[i >> 1] = fma2(q.y, E2[2 * i + 1], acc[i >> 1]);
        }
        unsigned long long b0 = add2(acc[0], acc[1]);
        unsigned long long b1 = add2(acc[2], acc[3]);
        unsigned long long b2 = add2(acc[4], acc[5]);
        unsigned long long b3 = add2(acc[6], acc[7]);
        unsigned long long c0 = add2(b0, b1);
        unsigned long long c1 = add2(b2, b3);
        unsigned long long d0 = add2(c0, c1);
        float lo, hi; unpack2(lo, hi, d0);
        float ssum = lo + hi;

        // p'_j = ssum * 2^(L*x_t) * 2^-K ; C += K  (skip entirely if masked)
        float pn = ssum * comb;
        if (!m) { pj = pn; Kacc += (float)K; }
        p_sh[pb ^ 1][j] = pj;

        xf_cur = xf_nx;
        xraw_n = xraw_2;
        __syncthreads();
    }

    // log_norm = ( lg2( sum_j p_final ) + Kacc ) / L
    red[j] = pj;
    __syncthreads();
    if (j == 0) {
        float sp = 0.f;
        for (int i = 0; i < CRF_T; i++) sp += red[i];
        red[0] = (lg2f(sp) + Kacc) / L;
    }
    __syncthreads();
    float log_norm = red[0];
    __syncthreads();

    red[j] = ub;
    __syncthreads();
    if (j == 0) {
        float su = 0.f;
        for (int i = 0; i < CRF_T; i++) su += red[i];
        g_partial[b] = -(su - log_norm);
        __threadfence();
        unsigned int v = atomicAdd(&g_count, 1u);
        is_last = (v == CRF_B - 1);
    }
    __syncthreads();

    if (is_last) {
        __threadfence();
        float s = 0.f;
        for (int i = j; i < CRF_B; i += CRF_T) s += g_partial[i];  // fixed order
        red[j] = s;
        __syncthreads();
        if (j == 0) {
            float tot = 0.f;
            for (int i = 0; i < CRF_T; i++) tot += red[i];
            out[0] = tot / (float)CRF_B;
            g_count = 0;   // reset for graph replay
        }
        for (int i = j; i < CRF_T * CRF_T && (1 + i) < out_size; i += CRF_T)
            out[1 + i] = trans[i];
    }
}

extern "C" void kernel_launch(void* const* d_in, const int* in_sizes, int n_in,
                              void* d_out, int out_size)
{
    const float* inputs = (const float*)d_in[0];
    const float* trans  = (const float*)d_in[1];
    const unsigned char* masks = (const unsigned char*)d_in[2];
    const int* tags = (const int*)d_in[3];
    float* out = (float*)d_out;

    crf_scan_kernel<<<CRF_B, CRF_T>>>(inputs, trans, masks, tags, out, out_size);
}